// round 3
// baseline (speedup 1.0000x reference)
#include <cuda_runtime.h>

// Fused upsample2x-bilinear -> affine_grid -> grid_sample_bilinear.
// Separable composition: output = 3x3 weighted sum over ORIGINAL image.
// R3: prepass repacks input into 2x-redundant float4 chunks (chunk j = cols
// 2j..2j+3), so the 3 x-taps are always ONE aligned LDG.128 per row.

#define N_   8
#define C_   32
#define HI   256
#define WI   256
#define HU   512
#define WU   512
#define WC   128   // chunks per row (WI/2)

// 8*32*256*128 float4 = 134 MB scratch (device global: allocation-free)
__device__ float4 g_chunks[N_ * C_ * HI * WC];

// ---------------- prepass: build overlapped chunks ----------------
__global__ void __launch_bounds__(256)
repack_chunks(const float* __restrict__ x) {
    int t = blockIdx.x * blockDim.x + threadIdx.x;   // one chunk per thread
    int j   = t & (WC - 1);
    int row = t >> 7;                                // (n*C + c)*HI + h
    const float* p = x + (long long)row * WI;
    int c0 = 2 * j;
    float4 v;
    v.x = p[c0];
    v.y = p[c0 + 1];
    v.z = p[min(c0 + 2, WI - 1)];
    v.w = p[min(c0 + 3, WI - 1)];
    g_chunks[t] = v;
}

// ---------------- main fused kernel ----------------
__device__ __forceinline__ void axis_taps(float f, int U, int O,
                                          int& base, float w[3]) {
    float f0 = floorf(f);
    int   i0 = (int)f0;
    float wf = f - f0;

    w[0] = 0.f; w[1] = 0.f; w[2] = 0.f;
    base = 0;

    #pragma unroll
    for (int k = 0; k < 2; k++) {
        int   t  = i0 + k;
        float Wk = (k == 0) ? (1.0f - wf) : wf;
        Wk = (t >= 0 && t < U) ? Wk : 0.0f;          // zero-padding validity
        int tc = min(max(t, 0), U - 1);
        float s  = fmaxf((float)tc * 0.5f - 0.25f, 0.0f);  // upsample source
        int   o0 = (int)s;
        float wu = s - (float)o0;
        int   o1 = min(o0 + 1, O - 1);
        if (k == 0) base = o0;                       // taps are monotone
        w[o0 - base] += Wk * (1.0f - wu);
        w[o1 - base] += Wk * wu;
    }
}

__global__ void __launch_bounds__(256)
fused_upsample_affine_sample(const float* __restrict__ theta,
                             float* __restrict__ out) {
    // 16x2 warp tiles: lane = (lx in [0,16), ly in [0,2))
    int wid  = blockIdx.x * 8 + (threadIdx.x >> 5);
    int lane = threadIdx.x & 31;
    int xo = ((wid & 31) << 4) | (lane & 15);          // 32 tiles of 16 in x
    int yo = (((wid >> 5) & 255) << 1) | (lane >> 4);  // 256 tiles of 2 in y
    int n  = wid >> 13;

    // affine grid (reference op order)
    float gxn = (2.0f * (float)xo + 1.0f) / (float)WU - 1.0f;
    float gyn = (2.0f * (float)yo + 1.0f) / (float)HU - 1.0f;
    const float* th = theta + n * 6;
    float gox = __ldg(th + 0) * gxn + __ldg(th + 1) * gyn + __ldg(th + 2);
    float goy = __ldg(th + 3) * gxn + __ldg(th + 4) * gyn + __ldg(th + 5);

    float ix = ((gox + 1.0f) * (float)WU - 1.0f) * 0.5f;
    float iy = ((goy + 1.0f) * (float)HU - 1.0f) * 0.5f;

    float* op = out + (((long long)n * C_) * (long long)(HU * WU))
                    + (long long)yo * WU + xo;

    int ix0 = (int)floorf(ix), iy0 = (int)floorf(iy);
    bool oob = (ix0 < -1) || (ix0 >= WU) || (iy0 < -1) || (iy0 >= HU)
               || !(ix == ix) || !(iy == iy);
    if (oob) {
        #pragma unroll 8
        for (int c = 0; c < C_; c++)
            op[(long long)c * (HU * WU)] = 0.0f;
        return;
    }

    int by, bx;
    float wy[3], wx[3];
    axis_taps(iy, HU, HI, by, wy);
    axis_taps(ix, WU, WI, bx, wx);

    // chunk j holds cols 2j..2j+3; taps bx..bx+2 sit at slots s0..s0+2
    int j  = bx >> 1;
    int s0 = bx & 1;
    float wv0 = (s0 == 0) ? wx[0] : 0.0f;
    float wv1 = (s0 == 0) ? wx[1] : wx[0];
    float wv2 = (s0 == 0) ? wx[2] : wx[1];
    float wv3 = (s0 == 0) ? 0.0f  : wx[2];

    float w00 = wy[0]*wv0, w01 = wy[0]*wv1, w02 = wy[0]*wv2, w03 = wy[0]*wv3;
    float w10 = wy[1]*wv0, w11 = wy[1]*wv1, w12 = wy[1]*wv2, w13 = wy[1]*wv3;
    float w20 = wy[2]*wv0, w21 = wy[2]*wv1, w22 = wy[2]*wv2, w23 = wy[2]*wv3;

    int r0 = min(by,     HI - 1) * WC + j;   // rows beyond edge have wy=0
    int r1 = min(by + 1, HI - 1) * WC + j;
    int r2 = min(by + 2, HI - 1) * WC + j;

    const float4* xp = g_chunks + (long long)n * C_ * (HI * WC);

    #pragma unroll 4
    for (int c = 0; c < C_; c++) {
        const float4* p = xp + c * (HI * WC);
        float4 a = __ldg(p + r0);
        float4 b = __ldg(p + r1);
        float4 d = __ldg(p + r2);

        float v = 0.0f;
        v = fmaf(w00, a.x, v); v = fmaf(w01, a.y, v);
        v = fmaf(w02, a.z, v); v = fmaf(w03, a.w, v);
        v = fmaf(w10, b.x, v); v = fmaf(w11, b.y, v);
        v = fmaf(w12, b.z, v); v = fmaf(w13, b.w, v);
        v = fmaf(w20, d.x, v); v = fmaf(w21, d.y, v);
        v = fmaf(w22, d.z, v); v = fmaf(w23, d.w, v);

        op[(long long)c * (HU * WU)] = v;
    }
}

extern "C" void kernel_launch(void* const* d_in, const int* in_sizes, int n_in,
                              void* d_out, int out_size) {
    const float* x     = (const float*)d_in[0];
    const float* theta = (const float*)d_in[1];
    float*       out   = (float*)d_out;

    // prepass: 8.39M chunks, one per thread
    repack_chunks<<<(N_ * C_ * HI * WC) / 256, 256>>>(x);
    // main: 65536 warps (16x2 tile each), 8 warps per block
    fused_upsample_affine_sample<<<8192, 256>>>(theta, out);
}